// round 14
// baseline (speedup 1.0000x reference)
#include <cuda_runtime.h>
#include <math.h>

#define B_TOTAL 500000
#define F 100
#define NT 10
#define C 10
#define H 7

#define BLOCK 128
#define PAIRS 25                              // u64 pairs per phase per row
#define SMEM_BYTES (2 * BLOCK * PAIRS * 8)    // 51200 B: double-buffered stage
#define CHUNKS ((B_TOTAL + BLOCK - 1) / BLOCK)   // 3907
#define GRID_CTAS (148 * 4)                   // persistent: one wave exactly

typedef unsigned long long u64;

// ---- packed f32x2 helpers (Blackwell sm_103a) ----
__device__ __forceinline__ u64 pk2(float lo, float hi) {
    u64 r; asm("mov.b64 %0,{%1,%2};" : "=l"(r) : "f"(lo), "f"(hi)); return r;
}
__device__ __forceinline__ void upk2(u64 v, float& lo, float& hi) {
    asm("mov.b64 {%0,%1},%2;" : "=f"(lo), "=f"(hi) : "l"(v));
}
__device__ __forceinline__ u64 ffma2(u64 a, u64 b, u64 c) {
    u64 d; asm("fma.rn.f32x2 %0,%1,%2,%3;" : "=l"(d) : "l"(a), "l"(b), "l"(c)); return d;
}
__device__ __forceinline__ void cp_async8(void* smem_dst, const void* gmem_src) {
    unsigned s = (unsigned)__cvta_generic_to_shared(smem_dst);
    asm volatile("cp.async.ca.shared.global [%0], [%1], 8;"
                 :: "r"(s), "l"(gmem_src) : "memory");
}
__device__ __forceinline__ void cp_commit() {
    asm volatile("cp.async.commit_group;" ::: "memory");
}
template<int N> __device__ __forceinline__ void cp_wait() {
    asm volatile("cp.async.wait_group %0;" :: "n"(N) : "memory");
}

// Precomputed affine parameters, aligned for LDC.128:
// A_t = Wt_t^T Wt_t - I, [t][c][i] i inner            [0,1000)
// c_t = Wt_t^T hbt_t + vbt_t, PADDED stride 16        [1000,1160)
// Ah  = Wh^T Wh, PADDED stride 16 per t               [1160,1320)
// ch  = Wh^T hbh + vbh                                [1320,1330)
#define P_A   0
#define P_C   1000
#define P_AH  1160
#define P_CH  1320
#define P_TOT 1332

__constant__ __align__(16) float cP[P_TOT];
__device__   __align__(16) float gP[P_TOT];

__global__ void precompute_params(const float* __restrict__ Wt,
                                  const float* __restrict__ hbt,
                                  const float* __restrict__ vbt,
                                  const float* __restrict__ Wh,
                                  const float* __restrict__ hbh,
                                  const float* __restrict__ vbh)
{
    for (int i = threadIdx.x; i < P_TOT; i += blockDim.x) gP[i] = 0.0f;
    __syncthreads();
    for (int idx = threadIdx.x; idx < 1210; idx += blockDim.x) {
        if (idx < 1000) {                       // A[t][c][i]
            int t = idx / 100, r = idx - t * 100;
            int c = r / 10, i = r - c * 10;
            float a = 0.0f;
            for (int h = 0; h < H; h++)
                a += Wt[(t * H + h) * C + i] * Wt[(t * H + h) * C + c];
            if (i == c) a -= 1.0f;
            gP[P_A + idx] = a;
        } else if (idx < 1100) {                // c_t[t][i] -> padded stride 16
            int e = idx - 1000;
            int t = e / 10, i = e - t * 10;
            float a = vbt[t * C + i];
            for (int h = 0; h < H; h++)
                a += Wt[(t * H + h) * C + i] * hbt[t * H + h];
            gP[P_C + t * 16 + i] = a;
        } else if (idx < 1200) {                // Ah[t][tp] -> padded stride 16
            int e = idx - 1100;
            int t = e / 10, tp = e - t * 10;
            float a = 0.0f;
            for (int h = 0; h < H; h++)
                a += Wh[h * NT + tp] * Wh[h * NT + t];
            gP[P_AH + t * 16 + tp] = a;
        } else {                                // ch[tp]
            int tp = idx - 1200;
            float a = vbh[tp];
            for (int h = 0; h < H; h++)
                a += Wh[h * NT + tp] * hbh[h];
            gP[P_CH + tp] = a;
        }
    }
}

// Stage one phase (25 pairs/row) of a chunk into buf; always commits a group.
__device__ __forceinline__ void fire_phase(u64* __restrict__ buf,
                                           const u64* __restrict__ xg8,
                                           long long rowBase, int warp, int lane,
                                           int phase, bool enable)
{
    if (enable && lane < PAIRS) {
        const int r0 = warp * 32;
        #pragma unroll 8
        for (int j = 0; j < 32; j++) {
            const long long gr = rowBase + r0 + j;
            if (gr < B_TOTAL)
                cp_async8(&buf[(r0 + j) * PAIRS + lane],
                          xg8 + gr * 50 + phase * PAIRS + lane);
        }
    }
    cp_commit();   // empty group when disabled keeps the FIFO count invariant
}

__device__ __forceinline__ void compute_phase(const u64* __restrict__ row,
                                              int p, float* tails)
{
    const ulonglong2* cA4 = reinterpret_cast<const ulonglong2*>(cP + P_A);
    const ulonglong2* cC4 = reinterpret_cast<const ulonglong2*>(cP + P_C);
    const u64*        cC2 = reinterpret_cast<const u64*>(cP + P_C);

    #pragma unroll
    for (int tt = 0; tt < NT / 2; tt++) {
        const int t = p * (NT / 2) + tt;

        u64 xc[5];
        #pragma unroll
        for (int j = 0; j < 5; j++) xc[j] = row[tt * 5 + j];

        u64 D[5];
        {
            ulonglong2 c01 = cC4[t * 4 + 0];
            ulonglong2 c23 = cC4[t * 4 + 1];
            D[0] = c01.x; D[1] = c01.y; D[2] = c23.x; D[3] = c23.y;
            D[4] = cC2[t * 8 + 4];
        }

        #pragma unroll
        for (int cp = 0; cp < 5; cp++) {
            float lo, hi; upk2(xc[cp], lo, hi);
            const u64 b0 = pk2(lo, lo);
            const u64 b1 = pk2(hi, hi);
            const int base = t * 25 + cp * 5;   // ulonglong2 index
            ulonglong2 v0 = cA4[base + 0];
            ulonglong2 v1 = cA4[base + 1];
            ulonglong2 v2 = cA4[base + 2];
            ulonglong2 v3 = cA4[base + 3];
            ulonglong2 v4 = cA4[base + 4];
            D[0] = ffma2(b0, v0.x, D[0]);
            D[1] = ffma2(b0, v0.y, D[1]);
            D[2] = ffma2(b0, v1.x, D[2]);
            D[3] = ffma2(b0, v1.y, D[3]);
            D[4] = ffma2(b0, v2.x, D[4]);
            D[0] = ffma2(b1, v2.y, D[0]);
            D[1] = ffma2(b1, v3.x, D[1]);
            D[2] = ffma2(b1, v3.y, D[2]);
            D[3] = ffma2(b1, v4.x, D[3]);
            D[4] = ffma2(b1, v4.y, D[4]);
        }

        u64 s2 = 0ULL;
        #pragma unroll
        for (int ip = 0; ip < 5; ip++) s2 = ffma2(D[ip], D[ip], s2);
        float slo, shi; upk2(s2, slo, shi);
        tails[t] = 0.5f * __logf(slo + shi) - 1.1512925465f;  // log(sqrt(sse/10))
    }
}

__global__ __launch_bounds__(BLOCK, 4)
void kitnet_kernel(const float* __restrict__ x,
                   float* __restrict__ out_head,   // [B,NT]
                   float* __restrict__ out_tails)  // [B,NT]
{
    extern __shared__ __align__(16) u64 s8[];   // [2][BLOCK][25]
    u64* buf0 = s8;
    u64* buf1 = s8 + BLOCK * PAIRS;

    const int tid  = threadIdx.x;
    const int lane = tid & 31;
    const int warp = tid >> 5;
    const u64* xg8 = reinterpret_cast<const u64*>(x);

    const int stride = gridDim.x;

    // ---- prologue: fire both phases of this CTA's first chunk ----
    long long chunk = blockIdx.x;
    fire_phase(buf0, xg8, chunk * BLOCK, warp, lane, 0, chunk < CHUNKS);
    fire_phase(buf1, xg8, chunk * BLOCK, warp, lane, 1, chunk < CHUNKS);

    const ulonglong2* cAh4 = reinterpret_cast<const ulonglong2*>(cP + P_AH);
    const u64*        cAh2 = reinterpret_cast<const u64*>(cP + P_AH);
    const u64*        cCh2 = reinterpret_cast<const u64*>(cP + P_CH);

    for (; chunk < CHUNKS; chunk += stride) {
        const long long rowBase  = chunk * BLOCK;
        const long long nextBase = (chunk + stride) * BLOCK;
        const bool hasNext = (chunk + stride) < CHUNKS;

        float tails[NT];

        // ---- phase 0: trees 0..4 ----  in flight: [ph0(k), ph1(k)]
        cp_wait<1>();
        __syncthreads();
        compute_phase(buf0 + tid * PAIRS, 0, tails);
        __syncthreads();                        // all buf0 reads complete
        fire_phase(buf0, xg8, nextBase, warp, lane, 0, hasNext);
        // in flight: [ph1(k), ph0(k+1)]

        // ---- phase 1: trees 5..9 ----
        cp_wait<1>();
        __syncthreads();
        compute_phase(buf1 + tid * PAIRS, 1, tails);

        // ---- head: head_out = Ah tails + ch ----
        u64 ho[5];
        #pragma unroll
        for (int ip = 0; ip < 5; ip++) ho[ip] = cCh2[ip];
        #pragma unroll
        for (int t = 0; t < NT; t++) {
            const u64 tb = pk2(tails[t], tails[t]);
            ulonglong2 a01 = cAh4[t * 4 + 0];
            ulonglong2 a23 = cAh4[t * 4 + 1];
            u64 a4 = cAh2[t * 8 + 4];
            ho[0] = ffma2(tb, a01.x, ho[0]);
            ho[1] = ffma2(tb, a01.y, ho[1]);
            ho[2] = ffma2(tb, a23.x, ho[2]);
            ho[3] = ffma2(tb, a23.y, ho[3]);
            ho[4] = ffma2(tb, a4,    ho[4]);
        }

        // ---- bounce outputs into own buf1 row (thread-local; no sync needed) ----
        {
            u64* slot = buf1 + tid * PAIRS;
            #pragma unroll
            for (int k = 0; k < 5; k++) slot[k] = ho[k];
            #pragma unroll
            for (int k = 0; k < 5; k++)
                slot[5 + k] = pk2(tails[2 * k], tails[2 * k + 1]);
        }
        __syncthreads();

        // ---- coalesced stores from buf1 ----
        {
            u64* oh = reinterpret_cast<u64*>(out_head);
            u64* ot = reinterpret_cast<u64*>(out_tails);
            const long long base = rowBase * 5;           // u64 units
            const long long lim  = (long long)B_TOTAL * 5;
            #pragma unroll
            for (int i = 0; i < 5; i++) {
                const int m = i * BLOCK + tid;            // 0..639
                const int r = m / 5, j = m - r * 5;
                if (base + m < lim) {
                    oh[base + m] = buf1[r * PAIRS + j];
                    ot[base + m] = buf1[r * PAIRS + 5 + j];
                }
            }
        }
        __syncthreads();                        // all buf1 reads complete
        fire_phase(buf1, xg8, nextBase, warp, lane, 1, hasNext);
        // in flight: [ph0(k+1), ph1(k+1)] — loop invariant restored
    }
}

extern "C" void kernel_launch(void* const* d_in, const int* in_sizes, int n_in,
                              void* d_out, int out_size) {
    const float* x = (const float*)d_in[0];
    // d_in[7] = clusters: arange identity by construction -> unused.

    float* out = (float*)d_out;
    float* out_head  = out;                            // [B, NT]
    float* out_tails = out + (long long)B_TOTAL * NT;  // [B, NT]

    static void* cP_addr = nullptr;
    static void* gP_addr = nullptr;
    static bool init_done = false;
    if (!init_done) {
        cudaGetSymbolAddress(&cP_addr, cP);
        cudaGetSymbolAddress(&gP_addr, gP);
        cudaFuncSetAttribute(kitnet_kernel,
                             cudaFuncAttributeMaxDynamicSharedMemorySize,
                             SMEM_BYTES);
        init_done = true;
    }

    precompute_params<<<1, 1024>>>((const float*)d_in[1], (const float*)d_in[2],
                                   (const float*)d_in[3], (const float*)d_in[4],
                                   (const float*)d_in[5], (const float*)d_in[6]);
    cudaMemcpyAsync(cP_addr, gP_addr, P_TOT * 4, cudaMemcpyDeviceToDevice);

    const int blocks = (CHUNKS < GRID_CTAS) ? CHUNKS : GRID_CTAS;
    kitnet_kernel<<<blocks, BLOCK, SMEM_BYTES>>>(x, out_head, out_tails);
}